// round 15
// baseline (speedup 1.0000x reference)
#include <cuda_runtime.h>
#include <cuda_bf16.h>
#include <math.h>

#define NN 100000
#define EE 1600000
#define FIN 1024
#define HH 128
#define NOUT 32
#define BNP 1024

// ---------------- scratch (static __device__, referenced only from device code) ----------------
__device__ float g_buf0[(size_t)NN * HH];   // GEMM output h2
__device__ float g_buf1[(size_t)NN * HH];   // aggregate output
__device__ float g_as[NN], g_ad[NN];
__device__ int   g_cnt[NN], g_rs[NN], g_fill[NN];
__device__ int   g_csr[EE];
__device__ int   g_csum[128], g_coff[128];
__device__ float g_mu[HH], g_istd[HH];
__device__ float g_part[BNP * HH];
__device__ float g_part2[BNP * HH];
__device__ int   g_is64;            // 1 if edge_index is int64, 0 if int32
__device__ unsigned g_asmax_bits;   // order-invariant float max encoding

// ---------------- helpers ----------------
__device__ __forceinline__ unsigned long long pack2(float lo, float hi) {
    unsigned long long r;
    asm("mov.b64 %0, {%1, %2};" : "=l"(r) : "f"(lo), "f"(hi));
    return r;
}
__device__ __forceinline__ unsigned long long fma2(unsigned long long a,
                                                   unsigned long long b,
                                                   unsigned long long c) {
    asm("fma.rn.f32x2 %0, %1, %2, %3;" : "=l"(c) : "l"(a), "l"(b), "l"(c));
    return c;
}
__device__ __forceinline__ float bnlrelu(float v, float m, float is, float g, float b) {
    float t = (v - m) * is * g + b;
    return t > 0.f ? t : 0.2f * t;
}
__device__ __forceinline__ unsigned fkey(float f) {
    unsigned b = __float_as_uint(f);
    return (b & 0x80000000u) ? ~b : (b | 0x80000000u);
}
__device__ __forceinline__ float funkey(unsigned k) {
    unsigned b = (k & 0x80000000u) ? (k & 0x7fffffffu) : ~k;
    return __uint_as_float(b);
}
// split (even,odd) pair into bf16 hi/lo packed words (even in low 16 bits)
__device__ __forceinline__ void split_pack(float e, float o, unsigned& hi, unsigned& lo) {
    __nv_bfloat16 he = __float2bfloat16_rn(e);
    __nv_bfloat16 ho = __float2bfloat16_rn(o);
    float re = e - __bfloat162float(he);
    float ro = o - __bfloat162float(ho);
    __nv_bfloat162 hp = __halves2bfloat162(he, ho);
    __nv_bfloat162 lp = __halves2bfloat162(__float2bfloat16_rn(re), __float2bfloat16_rn(ro));
    hi = *reinterpret_cast<unsigned*>(&hp);
    lo = *reinterpret_cast<unsigned*>(&lp);
}
__device__ __forceinline__ void mma_bf16(float c[4], const unsigned a[4], const unsigned b[2]) {
    asm volatile(
        "mma.sync.aligned.m16n8k16.row.col.f32.bf16.bf16.f32 "
        "{%0,%1,%2,%3}, {%4,%5,%6,%7}, {%8,%9}, {%0,%1,%2,%3};"
        : "+f"(c[0]), "+f"(c[1]), "+f"(c[2]), "+f"(c[3])
        : "r"(a[0]), "r"(a[1]), "r"(a[2]), "r"(a[3]), "r"(b[0]), "r"(b[1]));
}
// edge accessors: e is the raw buffer as int32 words
__device__ __forceinline__ int edge_src(const int* e, int i) {
    return g_is64 ? (int)((const long long*)e)[i] : e[i];
}
__device__ __forceinline__ int edge_dst(const int* e, int i) {
    return g_is64 ? (int)((const long long*)e)[EE + i] : e[EE + i];
}

// ---------------- kernels ----------------
__global__ void detect_kernel(const int* __restrict__ e) {
    if (threadIdx.x == 0 && blockIdx.x == 0) {
        int z = 0;
#pragma unroll
        for (int k = 1; k <= 15; k += 2) z |= e[k];   // high words if int64
        g_is64 = (z == 0) ? 1 : 0;
    }
}

__global__ void zero_int2_kernel() {
    int i = blockIdx.x * blockDim.x + threadIdx.x;
    if (i < NN) { g_cnt[i] = 0; g_fill[i] = 0; }
}

__global__ void hist_kernel(const int* __restrict__ edges) {
    int i = blockIdx.x * blockDim.x + threadIdx.x;
    if (i < EE) {
        int d = edge_dst(edges, i);
        if ((unsigned)d < (unsigned)NN) atomicAdd(&g_cnt[d], 1);
    }
}

__global__ void scan1_kernel() {
    __shared__ int sh[1024];
    int i = blockIdx.x * 1024 + threadIdx.x;
    int v = (i < NN) ? g_cnt[i] : 0;
    sh[threadIdx.x] = v;
    __syncthreads();
    for (int off = 1; off < 1024; off <<= 1) {
        int t = (threadIdx.x >= off) ? sh[threadIdx.x - off] : 0;
        __syncthreads();
        sh[threadIdx.x] += t;
        __syncthreads();
    }
    if (i < NN) g_rs[i] = sh[threadIdx.x];          // inclusive, fixed up later
    if (threadIdx.x == 1023) g_csum[blockIdx.x] = sh[1023];
}

__global__ void scan2_kernel(int nchunks) {
    if (threadIdx.x == 0 && blockIdx.x == 0) {
        int run = 0;
        for (int c = 0; c < nchunks; c++) { g_coff[c] = run; run += g_csum[c]; }
    }
}

__global__ void scan3_kernel() {
    int i = blockIdx.x * blockDim.x + threadIdx.x;
    if (i < NN) g_rs[i] = g_rs[i] - g_cnt[i] + g_coff[i >> 10];  // exclusive start
}

__global__ void scatter_kernel(const int* __restrict__ edges) {
    int i = blockIdx.x * blockDim.x + threadIdx.x;
    if (i < EE) {
        int s = edge_src(edges, i);
        int d = edge_dst(edges, i);
        if ((unsigned)d < (unsigned)NN && (unsigned)s < (unsigned)NN) {
            int pos = g_rs[d] + atomicAdd(&g_fill[d], 1);
            if ((unsigned)pos < (unsigned)EE) g_csr[pos] = s;
        }
    }
}

// global max of g_as (order-invariant -> deterministic)
__global__ void reset_asmax_kernel() {
    if (threadIdx.x == 0) g_asmax_bits = 0u;   // below key(-inf)
}
__global__ void asmax_kernel() {
    int i = blockIdx.x * blockDim.x + threadIdx.x;
    float v = (i < NN) ? g_as[i] : -INFINITY;
#pragma unroll
    for (int o = 16; o; o >>= 1) v = fmaxf(v, __shfl_xor_sync(0xffffffffu, v, o));
    __shared__ float sm[32];
    int lane = threadIdx.x & 31, w = threadIdx.x >> 5;
    if (lane == 0) sm[w] = v;
    __syncthreads();
    if (w == 0) {
        v = (lane < (blockDim.x >> 5)) ? sm[lane] : -INFINITY;
#pragma unroll
        for (int o = 16; o; o >>= 1) v = fmaxf(v, __shfl_xor_sync(0xffffffffu, v, o));
        if (lane == 0) atomicMax(&g_asmax_bits, fkey(v));
    }
}

// ---------------- layer-0 GEMM: bf16x2 compensated tensor cores ----------------
// Fused: rowsum (-> out_l + scale), log1p preprocess, GEMM, alpha epilogue.
#define SPITCH 136
__global__ void __launch_bounds__(256)
gemm0_bf16x2_kernel(const float* __restrict__ A, const float* __restrict__ W,
                    float* __restrict__ out_l,
                    const float* __restrict__ a_s, const float* __restrict__ a_d) {
    __shared__ unsigned As_hi[16 * SPITCH];
    __shared__ unsigned As_lo[16 * SPITCH];
    __shared__ unsigned Bs_hi[16 * SPITCH];
    __shared__ unsigned Bs_lo[16 * SPITCH];
    __shared__ float sc_sh[128];
    __shared__ float sAs[128], sAd[128];
    int tid = threadIdx.x;
    int lane = tid & 31;
    int warpId = tid >> 5;
    int blockRow = blockIdx.x * 128;
    int grp = lane >> 2;        // 0..7
    int qid = lane & 3;         // 0..3
    int m0 = warpId * 16 + grp;

    if (tid < 128) { sAs[tid] = __ldg(&a_s[tid]); sAd[tid] = __ldg(&a_d[tid]); }

    // ---- fused rowsum pre-pass ----
    {
        const float4* xv = (const float4*)A;
#pragma unroll 1
        for (int rr = 0; rr < 16; rr++) {
            int r = warpId * 16 + rr;
            int row = blockRow + r;
            float s = 0.f;
            if (row < NN) {
                size_t base = (size_t)row * 256;
#pragma unroll
                for (int i = 0; i < 8; i++) {
                    float4 v = __ldg(&xv[base + lane + i * 32]);
                    s += v.x + v.y + v.z + v.w;
                }
            }
#pragma unroll
            for (int o = 16; o; o >>= 1) s += __shfl_xor_sync(0xffffffffu, s, o);
            if (lane == 0 && row < NN) {
                out_l[row] = s;
                sc_sh[r] = 10000.0f / s;
            }
        }
    }
    __syncthreads();

    float c[16][4];
#pragma unroll
    for (int nt = 0; nt < 16; nt++)
#pragma unroll
        for (int j = 0; j < 4; j++) c[nt][j] = 0.f;

    for (int k0 = 0; k0 < FIN; k0 += 32) {
#pragma unroll
        for (int i = 0; i < 4; i++) {
            int f = tid + i * 256;
            int r = f >> 3;
            int kq = (f & 7) << 2;
            int row = blockRow + r;
            float4 v = make_float4(0.f, 0.f, 0.f, 0.f);
            if (row < NN) {
                v = __ldg((const float4*)&A[(size_t)row * FIN + k0 + kq]);
                float sc = sc_sh[r];
                v.x = log1pf(v.x * sc); v.y = log1pf(v.y * sc);
                v.z = log1pf(v.z * sc); v.w = log1pf(v.w * sc);
            }
            unsigned h0, l0, h1, l1;
            split_pack(v.x, v.y, h0, l0);
            split_pack(v.z, v.w, h1, l1);
            int kp = kq >> 1;
            As_hi[(kp + 0) * SPITCH + r] = h0;
            As_lo[(kp + 0) * SPITCH + r] = l0;
            As_hi[(kp + 1) * SPITCH + r] = h1;
            As_lo[(kp + 1) * SPITCH + r] = l1;
        }
#pragma unroll
        for (int i = 0; i < 2; i++) {
            int f = tid + i * 256;
            int kp = f >> 5;
            int n4 = (f & 31) << 2;
            float4 ve = __ldg((const float4*)&W[(size_t)(k0 + 2 * kp) * 128 + n4]);
            float4 vo = __ldg((const float4*)&W[(size_t)(k0 + 2 * kp + 1) * 128 + n4]);
            unsigned h, l;
            split_pack(ve.x, vo.x, h, l);
            Bs_hi[kp * SPITCH + n4 + 0] = h; Bs_lo[kp * SPITCH + n4 + 0] = l;
            split_pack(ve.y, vo.y, h, l);
            Bs_hi[kp * SPITCH + n4 + 1] = h; Bs_lo[kp * SPITCH + n4 + 1] = l;
            split_pack(ve.z, vo.z, h, l);
            Bs_hi[kp * SPITCH + n4 + 2] = h; Bs_lo[kp * SPITCH + n4 + 2] = l;
            split_pack(ve.w, vo.w, h, l);
            Bs_hi[kp * SPITCH + n4 + 3] = h; Bs_lo[kp * SPITCH + n4 + 3] = l;
        }
        __syncthreads();
#pragma unroll
        for (int kk = 0; kk < 2; kk++) {
            int kpb = kk * 8;
            unsigned ah[4], al[4];
            ah[0] = As_hi[(kpb + qid) * SPITCH + m0];
            ah[1] = As_hi[(kpb + qid) * SPITCH + m0 + 8];
            ah[2] = As_hi[(kpb + qid + 4) * SPITCH + m0];
            ah[3] = As_hi[(kpb + qid + 4) * SPITCH + m0 + 8];
            al[0] = As_lo[(kpb + qid) * SPITCH + m0];
            al[1] = As_lo[(kpb + qid) * SPITCH + m0 + 8];
            al[2] = As_lo[(kpb + qid + 4) * SPITCH + m0];
            al[3] = As_lo[(kpb + qid + 4) * SPITCH + m0 + 8];
#pragma unroll
            for (int nt = 0; nt < 16; nt++) {
                int nb = nt * 8 + grp;
                unsigned bh[2], bl[2];
                bh[0] = Bs_hi[(kpb + qid) * SPITCH + nb];
                bh[1] = Bs_hi[(kpb + qid + 4) * SPITCH + nb];
                bl[0] = Bs_lo[(kpb + qid) * SPITCH + nb];
                bl[1] = Bs_lo[(kpb + qid + 4) * SPITCH + nb];
                mma_bf16(c[nt], ah, bh);
                mma_bf16(c[nt], ah, bl);
                mma_bf16(c[nt], al, bh);
            }
        }
        __syncthreads();
    }
    int r0 = blockRow + m0;
    int r1 = r0 + 8;
    float ds0 = 0.f, dd0 = 0.f, ds1 = 0.f, dd1 = 0.f;
#pragma unroll
    for (int nt = 0; nt < 16; nt++) {
        int col = nt * 8 + qid * 2;
        float w0 = sAs[col], w1 = sAs[col + 1];
        float u0 = sAd[col], u1 = sAd[col + 1];
        ds0 += c[nt][0] * w0 + c[nt][1] * w1;
        dd0 += c[nt][0] * u0 + c[nt][1] * u1;
        ds1 += c[nt][2] * w0 + c[nt][3] * w1;
        dd1 += c[nt][2] * u0 + c[nt][3] * u1;
        if (r0 < NN) {
            float2 v0 = make_float2(c[nt][0], c[nt][1]);
            *(float2*)&g_buf0[(size_t)r0 * 128 + col] = v0;
        }
        if (r1 < NN) {
            float2 v1 = make_float2(c[nt][2], c[nt][3]);
            *(float2*)&g_buf0[(size_t)r1 * 128 + col] = v1;
        }
    }
#pragma unroll
    for (int o = 1; o < 4; o <<= 1) {
        ds0 += __shfl_xor_sync(0xffffffffu, ds0, o);
        dd0 += __shfl_xor_sync(0xffffffffu, dd0, o);
        ds1 += __shfl_xor_sync(0xffffffffu, ds1, o);
        dd1 += __shfl_xor_sync(0xffffffffu, dd1, o);
    }
    if (qid == 0) {
        if (r0 < NN) { g_as[r0] = ds0; g_ad[r0] = dd0; }
        if (r1 < NN) { g_as[r1] = ds1; g_ad[r1] = dd1; }
    }
}

// ---------------- layer-1 GEMM: fp32 f32x2 path (K=128), fused alpha ----------------
__global__ void __launch_bounds__(256)
gemm1_kernel(const float* __restrict__ W,
             const float* __restrict__ gam, const float* __restrict__ bet,
             const float* __restrict__ a_s, const float* __restrict__ a_d) {
    const float* A = (const float*)g_buf1;
    __shared__ float As[16][128];
    __shared__ float Bs[16][128];
    int tid = threadIdx.x;
    int lane = tid & 31;
    int blockRow = blockIdx.x * 128;
    int tm = (tid >> 4) << 3;
    int tn = (tid & 15) << 3;
    unsigned long long acc[8][4];
#pragma unroll
    for (int i = 0; i < 8; i++)
#pragma unroll
        for (int j = 0; j < 4; j++) acc[i][j] = 0ull;

    for (int k0 = 0; k0 < HH; k0 += 16) {
#pragma unroll
        for (int i = 0; i < 2; i++) {
            int f = tid + i * 256;
            int r = f >> 2, kq = (f & 3) << 2;
            int row = blockRow + r;
            float4 v = make_float4(0.f, 0.f, 0.f, 0.f);
            if (row < NN) {
                v = __ldg((const float4*)&A[(size_t)row * HH + k0 + kq]);
                float4 m4 = *(const float4*)&g_mu[k0 + kq];
                float4 i4 = *(const float4*)&g_istd[k0 + kq];
                float4 g4 = __ldg((const float4*)&gam[k0 + kq]);
                float4 b4 = __ldg((const float4*)&bet[k0 + kq]);
                v.x = bnlrelu(v.x, m4.x, i4.x, g4.x, b4.x);
                v.y = bnlrelu(v.y, m4.y, i4.y, g4.y, b4.y);
                v.z = bnlrelu(v.z, m4.z, i4.z, g4.z, b4.z);
                v.w = bnlrelu(v.w, m4.w, i4.w, g4.w, b4.w);
            }
            As[kq + 0][r] = v.x; As[kq + 1][r] = v.y;
            As[kq + 2][r] = v.z; As[kq + 3][r] = v.w;
        }
#pragma unroll
        for (int i = 0; i < 2; i++) {
            int f = tid + i * 256;
            int kr = f >> 5, c4 = (f & 31) << 2;
            float4 v = __ldg((const float4*)&W[(size_t)(k0 + kr) * 128 + c4]);
            *(float4*)&Bs[kr][c4] = v;
        }
        __syncthreads();
#pragma unroll
        for (int kk = 0; kk < 16; kk++) {
            float4 a0 = *(const float4*)&As[kk][tm];
            float4 a1 = *(const float4*)&As[kk][tm + 4];
            float4 b0 = *(const float4*)&Bs[kk][tn];
            float4 b1 = *(const float4*)&Bs[kk][tn + 4];
            unsigned long long bp[4] = {pack2(b0.x, b0.y), pack2(b0.z, b0.w),
                                        pack2(b1.x, b1.y), pack2(b1.z, b1.w)};
            float av[8] = {a0.x, a0.y, a0.z, a0.w, a1.x, a1.y, a1.z, a1.w};
#pragma unroll
            for (int i = 0; i < 8; i++) {
                unsigned long long aa = pack2(av[i], av[i]);
#pragma unroll
                for (int j = 0; j < 4; j++) acc[i][j] = fma2(aa, bp[j], acc[i][j]);
            }
        }
        __syncthreads();
    }
    float4 as0 = __ldg((const float4*)&a_s[tn]);
    float4 as1 = __ldg((const float4*)&a_s[tn + 4]);
    float4 ad0 = __ldg((const float4*)&a_d[tn]);
    float4 ad1 = __ldg((const float4*)&a_d[tn + 4]);
#pragma unroll
    for (int i = 0; i < 8; i++) {
        int row = blockRow + tm + i;
        float2 f0 = *(float2*)&acc[i][0];
        float2 f1 = *(float2*)&acc[i][1];
        float2 f2 = *(float2*)&acc[i][2];
        float2 f3 = *(float2*)&acc[i][3];
        float dsv = f0.x * as0.x + f0.y * as0.y + f1.x * as0.z + f1.y * as0.w
                  + f2.x * as1.x + f2.y * as1.y + f3.x * as1.z + f3.y * as1.w;
        float ddv = f0.x * ad0.x + f0.y * ad0.y + f1.x * ad0.z + f1.y * ad0.w
                  + f2.x * ad1.x + f2.y * ad1.y + f3.x * ad1.z + f3.y * ad1.w;
#pragma unroll
        for (int o = 1; o < 16; o <<= 1) {
            dsv += __shfl_xor_sync(0xffffffffu, dsv, o);
            ddv += __shfl_xor_sync(0xffffffffu, ddv, o);
        }
        if (row < NN) {
            unsigned long long* cp = (unsigned long long*)&g_buf0[(size_t)row * 128 + tn];
#pragma unroll
            for (int j = 0; j < 4; j++) cp[j] = acc[i][j];
            if ((lane & 15) == 0) { g_as[row] = dsv; g_ad[row] = ddv; }
        }
    }
}

// GAT softmax-aggregate via CSR, warp per dst node: g_buf0 -> g_buf1
// Single pass: M_d = leaky(global_max(as) + ad[d]) >= all edge logits (leaky monotone).
__global__ void aggregate_kernel() {
    int lane = threadIdx.x & 31;
    int warp = (blockIdx.x * blockDim.x + threadIdx.x) >> 5;
    int nw = (gridDim.x * blockDim.x) >> 5;
    const float4* h2v = (const float4*)g_buf0;
    float amax = funkey(g_asmax_bits);
    for (int d = warp; d < NN; d += nw) {
        int deg = g_cnt[d];
        int st = g_rs[d];
        float ad = g_ad[d];
        float ebound = amax + ad;
        float mx = ebound > 0.f ? ebound : 0.2f * ebound;
        float4 acc = make_float4(0.f, 0.f, 0.f, 0.f);
        float dsum = 0.f;
        for (int base = 0; base < deg; base += 32) {
            int nch = min(32, deg - base);
            int s_my = 0; float w_my = 0.f;
            if (lane < nch) {
                s_my = g_csr[st + base + lane];
                float e = g_as[s_my] + ad;
                e = e > 0.f ? e : 0.2f * e;
                w_my = __expf(e - mx);
                dsum += w_my;
            }
            int j = 0;
            for (; j + 3 < nch; j += 4) {
                int s0 = __shfl_sync(0xffffffffu, s_my, j);
                int s1 = __shfl_sync(0xffffffffu, s_my, j + 1);
                int s2 = __shfl_sync(0xffffffffu, s_my, j + 2);
                int s3 = __shfl_sync(0xffffffffu, s_my, j + 3);
                float w0 = __shfl_sync(0xffffffffu, w_my, j);
                float w1 = __shfl_sync(0xffffffffu, w_my, j + 1);
                float w2 = __shfl_sync(0xffffffffu, w_my, j + 2);
                float w3 = __shfl_sync(0xffffffffu, w_my, j + 3);
                float4 v0 = __ldg(&h2v[(size_t)s0 * 32 + lane]);
                float4 v1 = __ldg(&h2v[(size_t)s1 * 32 + lane]);
                float4 v2 = __ldg(&h2v[(size_t)s2 * 32 + lane]);
                float4 v3 = __ldg(&h2v[(size_t)s3 * 32 + lane]);
                acc.x = fmaf(w0, v0.x, acc.x); acc.y = fmaf(w0, v0.y, acc.y);
                acc.z = fmaf(w0, v0.z, acc.z); acc.w = fmaf(w0, v0.w, acc.w);
                acc.x = fmaf(w1, v1.x, acc.x); acc.y = fmaf(w1, v1.y, acc.y);
                acc.z = fmaf(w1, v1.z, acc.z); acc.w = fmaf(w1, v1.w, acc.w);
                acc.x = fmaf(w2, v2.x, acc.x); acc.y = fmaf(w2, v2.y, acc.y);
                acc.z = fmaf(w2, v2.z, acc.z); acc.w = fmaf(w2, v2.w, acc.w);
                acc.x = fmaf(w3, v3.x, acc.x); acc.y = fmaf(w3, v3.y, acc.y);
                acc.z = fmaf(w3, v3.z, acc.z); acc.w = fmaf(w3, v3.w, acc.w);
            }
            for (; j < nch; j++) {
                int s = __shfl_sync(0xffffffffu, s_my, j);
                float w = __shfl_sync(0xffffffffu, w_my, j);
                float4 v = __ldg(&h2v[(size_t)s * 32 + lane]);
                acc.x = fmaf(w, v.x, acc.x); acc.y = fmaf(w, v.y, acc.y);
                acc.z = fmaf(w, v.z, acc.z); acc.w = fmaf(w, v.w, acc.w);
            }
        }
#pragma unroll
        for (int o = 16; o; o >>= 1) dsum += __shfl_xor_sync(0xffffffffu, dsum, o);
        float inv = 1.0f / (dsum + 1e-16f);
        acc.x *= inv; acc.y *= inv; acc.z *= inv; acc.w *= inv;
        ((float4*)g_buf1)[(size_t)d * 32 + lane] = acc;
    }
}

// BN stats on g_buf1: single read pass (sum + sumsq), deterministic partials
__global__ void bn_stats_kernel() {
    int c = threadIdx.x;  // 128
    float s = 0.f, q = 0.f;
    for (int r = blockIdx.x; r < NN; r += gridDim.x) {
        float v = g_buf1[(size_t)r * 128 + c];
        s += v;
        q = fmaf(v, v, q);
    }
    g_part[blockIdx.x * 128 + c] = s;
    g_part2[blockIdx.x * 128 + c] = q;
}
__global__ void bn_finalize_kernel() {
    int c = threadIdx.x;
    float s = 0.f, q = 0.f;
    for (int p = 0; p < BNP; p++) {
        s += g_part[p * 128 + c];
        q += g_part2[p * 128 + c];
    }
    float mu = s / (float)NN;
    float var = q / (float)NN - mu * mu;
    var = var > 0.f ? var : 0.f;
    g_mu[c] = mu;
    g_istd[c] = rsqrtf(var + 1e-5f);
}

// heads on g_buf1
__global__ void __launch_bounds__(256)
heads_kernel(const float* __restrict__ gam, const float* __restrict__ bet,
             const float* __restrict__ locW, const float* __restrict__ locb,
             const float* __restrict__ stdW, const float* __restrict__ stdb,
             float* __restrict__ out_loc, float* __restrict__ out_std) {
    __shared__ float sL[128 * 32];
    __shared__ float sS[128 * 32];
    for (int i = threadIdx.x; i < 4096; i += 256) { sL[i] = locW[i]; sS[i] = stdW[i]; }
    __syncthreads();
    int lane = threadIdx.x & 31;
    int warp = (blockIdx.x * blockDim.x + threadIdx.x) >> 5;
    int nw = (gridDim.x * blockDim.x) >> 5;
    float4 m4 = *(const float4*)&g_mu[lane * 4];
    float4 i4 = *(const float4*)&g_istd[lane * 4];
    float4 g4 = __ldg((const float4*)&gam[lane * 4]);
    float4 b4 = __ldg((const float4*)&bet[lane * 4]);
    float lb = __ldg(&locb[lane]);
    float sb = __ldg(&stdb[lane]);
    for (int r = warp; r < NN; r += nw) {
        float4 v = *(const float4*)&g_buf1[(size_t)r * 128 + lane * 4];
        float vr[4];
        vr[0] = bnlrelu(v.x, m4.x, i4.x, g4.x, b4.x);
        vr[1] = bnlrelu(v.y, m4.y, i4.y, g4.y, b4.y);
        vr[2] = bnlrelu(v.z, m4.z, i4.z, g4.z, b4.z);
        vr[3] = bnlrelu(v.w, m4.w, i4.w, g4.w, b4.w);
        float al = 0.f, as = 0.f;
#pragma unroll
        for (int k4 = 0; k4 < 32; k4++) {
#pragma unroll
            for (int q = 0; q < 4; q++) {
                float vk = __shfl_sync(0xffffffffu, vr[q], k4);
                int k = k4 * 4 + q;
                al = fmaf(vk, sL[k * 32 + lane], al);
                as = fmaf(vk, sS[k * 32 + lane], as);
            }
        }
        out_loc[(size_t)r * 32 + lane] = al + lb;
        float z = as + sb;
        float sp = (z > 0.f) ? z + log1pf(__expf(-z)) : log1pf(__expf(z));
        out_std[(size_t)r * 32 + lane] = sp + 1e-7f;
    }
}

// ---------------- launch ----------------
extern "C" void kernel_launch(void* const* d_in, const int* in_sizes, int n_in,
                              void* d_out, int out_size) {
    const float* x = (const float*)d_in[0];
    const int* edges = (const int*)d_in[1];
    const float* W0 = (const float*)d_in[2];
    const float* a_s0 = (const float*)d_in[3];
    const float* a_d0 = (const float*)d_in[4];
    const float* g0 = (const float*)d_in[5];
    const float* b0 = (const float*)d_in[6];
    const float* W1 = (const float*)d_in[7];
    const float* a_s1 = (const float*)d_in[8];
    const float* a_d1 = (const float*)d_in[9];
    const float* g1 = (const float*)d_in[10];
    const float* b1 = (const float*)d_in[11];
    const float* locW = (const float*)d_in[12];
    const float* locb = (const float*)d_in[13];
    const float* stdW = (const float*)d_in[14];
    const float* stdb = (const float*)d_in[15];

    float* out = (float*)d_out;
    float* out_loc = out;
    float* out_std = out + (size_t)NN * NOUT;
    float* out_l = out + 2 * (size_t)NN * NOUT;

    const int CH = (NN + 1023) / 1024;  // 98

    detect_kernel<<<1, 32>>>(edges);
    zero_int2_kernel<<<(NN + 255) / 256, 256>>>();
    hist_kernel<<<(EE + 255) / 256, 256>>>(edges);
    scan1_kernel<<<CH, 1024>>>();
    scan2_kernel<<<1, 32>>>(CH);
    scan3_kernel<<<(NN + 255) / 256, 256>>>();
    scatter_kernel<<<(EE + 255) / 256, 256>>>(edges);

    // ---- layer 0 ----
    gemm0_bf16x2_kernel<<<(NN + 127) / 128, 256>>>(x, W0, out_l, a_s0, a_d0);
    reset_asmax_kernel<<<1, 32>>>();
    asmax_kernel<<<CH, 1024>>>();
    aggregate_kernel<<<12500, 256>>>();
    bn_stats_kernel<<<BNP, 128>>>();
    bn_finalize_kernel<<<1, 128>>>();

    // ---- layer 1 ----
    gemm1_kernel<<<(NN + 127) / 128, 256>>>(W1, g0, b0, a_s1, a_d1);
    reset_asmax_kernel<<<1, 32>>>();
    asmax_kernel<<<CH, 1024>>>();
    aggregate_kernel<<<12500, 256>>>();
    bn_stats_kernel<<<BNP, 128>>>();
    bn_finalize_kernel<<<1, 128>>>();

    // ---- heads ----
    heads_kernel<<<2048, 256>>>(g1, b1, locW, locb, stdW, stdb, out_loc, out_std);
}

// round 16
// speedup vs baseline: 1.0628x; 1.0628x over previous
#include <cuda_runtime.h>
#include <cuda_bf16.h>
#include <math.h>

#define NN 100000
#define EE 1600000
#define FIN 1024
#define HH 128
#define NOUT 32
#define BNP 1024

// ---------------- scratch (static __device__, referenced only from device code) ----------------
__device__ float g_buf0[(size_t)NN * HH];   // GEMM output h2
__device__ float g_buf1[(size_t)NN * HH];   // aggregate output
__device__ float g_as[NN], g_ad[NN];
__device__ int   g_cnt[NN], g_rs[NN], g_fill[NN];
__device__ int   g_csr[EE];
__device__ int   g_csum[128], g_coff[128];
__device__ float g_mu[HH], g_istd[HH];
__device__ float g_part[BNP * HH];
__device__ float g_part2[BNP * HH];
__device__ unsigned g_W0hi[512 * 128];      // W0 bf16 hi, [kpair][n]
__device__ unsigned g_W0lo[512 * 128];      // W0 bf16 lo
__device__ int   g_is64;            // 1 if edge_index is int64, 0 if int32
__device__ unsigned g_asmax_bits;   // order-invariant float max encoding

// ---------------- helpers ----------------
__device__ __forceinline__ unsigned long long pack2(float lo, float hi) {
    unsigned long long r;
    asm("mov.b64 %0, {%1, %2};" : "=l"(r) : "f"(lo), "f"(hi));
    return r;
}
__device__ __forceinline__ unsigned long long fma2(unsigned long long a,
                                                   unsigned long long b,
                                                   unsigned long long c) {
    asm("fma.rn.f32x2 %0, %1, %2, %3;" : "=l"(c) : "l"(a), "l"(b), "l"(c));
    return c;
}
__device__ __forceinline__ float bnlrelu(float v, float m, float is, float g, float b) {
    float t = (v - m) * is * g + b;
    return t > 0.f ? t : 0.2f * t;
}
__device__ __forceinline__ unsigned fkey(float f) {
    unsigned b = __float_as_uint(f);
    return (b & 0x80000000u) ? ~b : (b | 0x80000000u);
}
__device__ __forceinline__ float funkey(unsigned k) {
    unsigned b = (k & 0x80000000u) ? (k & 0x7fffffffu) : ~k;
    return __uint_as_float(b);
}
// split (even,odd) pair into bf16 hi/lo packed words (even in low 16 bits)
__device__ __forceinline__ void split_pack(float e, float o, unsigned& hi, unsigned& lo) {
    __nv_bfloat162 hp = __float22bfloat162_rn(make_float2(e, o));   // 1 cvt
    float he = __bfloat162float(__low2bfloat16(hp));                // shift
    float ho = __bfloat162float(__high2bfloat16(hp));
    __nv_bfloat162 lp = __float22bfloat162_rn(make_float2(e - he, o - ho));
    hi = *reinterpret_cast<unsigned*>(&hp);
    lo = *reinterpret_cast<unsigned*>(&lp);
}
__device__ __forceinline__ void mma_bf16(float c[4], const unsigned a[4], const unsigned b[2]) {
    asm volatile(
        "mma.sync.aligned.m16n8k16.row.col.f32.bf16.bf16.f32 "
        "{%0,%1,%2,%3}, {%4,%5,%6,%7}, {%8,%9}, {%0,%1,%2,%3};"
        : "+f"(c[0]), "+f"(c[1]), "+f"(c[2]), "+f"(c[3])
        : "r"(a[0]), "r"(a[1]), "r"(a[2]), "r"(a[3]), "r"(b[0]), "r"(b[1]));
}
// edge accessors: e is the raw buffer as int32 words
__device__ __forceinline__ int edge_src(const int* e, int i) {
    return g_is64 ? (int)((const long long*)e)[i] : e[i];
}
__device__ __forceinline__ int edge_dst(const int* e, int i) {
    return g_is64 ? (int)((const long long*)e)[EE + i] : e[EE + i];
}

// ---------------- kernels ----------------
__global__ void detect_kernel(const int* __restrict__ e) {
    if (threadIdx.x == 0 && blockIdx.x == 0) {
        int z = 0;
#pragma unroll
        for (int k = 1; k <= 15; k += 2) z |= e[k];   // high words if int64
        g_is64 = (z == 0) ? 1 : 0;
    }
}

__global__ void zero_int2_kernel() {
    int i = blockIdx.x * blockDim.x + threadIdx.x;
    if (i < NN) { g_cnt[i] = 0; g_fill[i] = 0; }
}

// one-time W0 bf16 hi/lo split, laid out [kpair][n] to mirror smem tiles
__global__ void w0prep_kernel(const float* __restrict__ W) {
    int i = blockIdx.x * blockDim.x + threadIdx.x;
    if (i < 512 * 128) {
        int kp = i >> 7, n = i & 127;
        float e = __ldg(&W[(size_t)(2 * kp) * 128 + n]);
        float o = __ldg(&W[(size_t)(2 * kp + 1) * 128 + n]);
        unsigned h, l;
        split_pack(e, o, h, l);
        g_W0hi[i] = h;
        g_W0lo[i] = l;
    }
}

// ---------------- layer-0 GEMM: bf16x2 compensated tensor cores ----------------
// Fused: rowsum (-> out_l + scale), fast log1p preprocess, GEMM, alpha epilogue.
#define SPITCH 136
__global__ void __launch_bounds__(256)
gemm0_bf16x2_kernel(const float* __restrict__ A,
                    float* __restrict__ out_l,
                    const float* __restrict__ a_s, const float* __restrict__ a_d) {
    __shared__ unsigned As_hi[16 * SPITCH];
    __shared__ unsigned As_lo[16 * SPITCH];
    __shared__ unsigned Bs_hi[16 * SPITCH];
    __shared__ unsigned Bs_lo[16 * SPITCH];
    __shared__ float sc_sh[128];
    __shared__ float sAs[128], sAd[128];
    int tid = threadIdx.x;
    int lane = tid & 31;
    int warpId = tid >> 5;
    int blockRow = blockIdx.x * 128;
    int grp = lane >> 2;        // 0..7
    int qid = lane & 3;         // 0..3
    int m0 = warpId * 16 + grp;

    if (tid < 128) { sAs[tid] = __ldg(&a_s[tid]); sAd[tid] = __ldg(&a_d[tid]); }

    // ---- fused rowsum pre-pass ----
    {
        const float4* xv = (const float4*)A;
#pragma unroll 1
        for (int rr = 0; rr < 16; rr++) {
            int r = warpId * 16 + rr;
            int row = blockRow + r;
            float s = 0.f;
            if (row < NN) {
                size_t base = (size_t)row * 256;
#pragma unroll
                for (int i = 0; i < 8; i++) {
                    float4 v = __ldg(&xv[base + lane + i * 32]);
                    s += v.x + v.y + v.z + v.w;
                }
            }
#pragma unroll
            for (int o = 16; o; o >>= 1) s += __shfl_xor_sync(0xffffffffu, s, o);
            if (lane == 0 && row < NN) {
                out_l[row] = s;
                sc_sh[r] = 10000.0f / s;
            }
        }
    }
    __syncthreads();

    float c[16][4];
#pragma unroll
    for (int nt = 0; nt < 16; nt++)
#pragma unroll
        for (int j = 0; j < 4; j++) c[nt][j] = 0.f;

    for (int k0 = 0; k0 < FIN; k0 += 32) {
        // A chunk: 128 rows x 32 k, fast log1p: x >= 0 so log(1+x) is safe
#pragma unroll
        for (int i = 0; i < 4; i++) {
            int f = tid + i * 256;
            int r = f >> 3;
            int kq = (f & 7) << 2;
            int row = blockRow + r;
            float4 v = make_float4(0.f, 0.f, 0.f, 0.f);
            if (row < NN) {
                v = __ldg((const float4*)&A[(size_t)row * FIN + k0 + kq]);
                float sc = sc_sh[r];
                v.x = __logf(fmaf(v.x, sc, 1.0f));
                v.y = __logf(fmaf(v.y, sc, 1.0f));
                v.z = __logf(fmaf(v.z, sc, 1.0f));
                v.w = __logf(fmaf(v.w, sc, 1.0f));
            }
            unsigned h0, l0, h1, l1;
            split_pack(v.x, v.y, h0, l0);
            split_pack(v.z, v.w, h1, l1);
            int kp = kq >> 1;
            As_hi[(kp + 0) * SPITCH + r] = h0;
            As_lo[(kp + 0) * SPITCH + r] = l0;
            As_hi[(kp + 1) * SPITCH + r] = h1;
            As_lo[(kp + 1) * SPITCH + r] = l1;
        }
        // B chunk: pre-split W0, plain uint4 copies
        {
            int kbase = (k0 >> 1) * 128;
#pragma unroll
            for (int i = 0; i < 2; i++) {
                int f = tid + i * 256;      // 0..511
                int kp = f >> 5;            // 0..15
                int n4 = (f & 31) << 2;     // 0..124
                uint4 h = *(const uint4*)&g_W0hi[kbase + kp * 128 + n4];
                uint4 l = *(const uint4*)&g_W0lo[kbase + kp * 128 + n4];
                Bs_hi[kp * SPITCH + n4 + 0] = h.x; Bs_lo[kp * SPITCH + n4 + 0] = l.x;
                Bs_hi[kp * SPITCH + n4 + 1] = h.y; Bs_lo[kp * SPITCH + n4 + 1] = l.y;
                Bs_hi[kp * SPITCH + n4 + 2] = h.z; Bs_lo[kp * SPITCH + n4 + 2] = l.z;
                Bs_hi[kp * SPITCH + n4 + 3] = h.w; Bs_lo[kp * SPITCH + n4 + 3] = l.w;
            }
        }
        __syncthreads();
#pragma unroll
        for (int kk = 0; kk < 2; kk++) {
            int kpb = kk * 8;
            unsigned ah[4], al[4];
            ah[0] = As_hi[(kpb + qid) * SPITCH + m0];
            ah[1] = As_hi[(kpb + qid) * SPITCH + m0 + 8];
            ah[2] = As_hi[(kpb + qid + 4) * SPITCH + m0];
            ah[3] = As_hi[(kpb + qid + 4) * SPITCH + m0 + 8];
            al[0] = As_lo[(kpb + qid) * SPITCH + m0];
            al[1] = As_lo[(kpb + qid) * SPITCH + m0 + 8];
            al[2] = As_lo[(kpb + qid + 4) * SPITCH + m0];
            al[3] = As_lo[(kpb + qid + 4) * SPITCH + m0 + 8];
#pragma unroll
            for (int nt = 0; nt < 16; nt++) {
                int nb = nt * 8 + grp;
                unsigned bh[2], bl[2];
                bh[0] = Bs_hi[(kpb + qid) * SPITCH + nb];
                bh[1] = Bs_hi[(kpb + qid + 4) * SPITCH + nb];
                bl[0] = Bs_lo[(kpb + qid) * SPITCH + nb];
                bl[1] = Bs_lo[(kpb + qid + 4) * SPITCH + nb];
                mma_bf16(c[nt], ah, bh);
                mma_bf16(c[nt], ah, bl);
                mma_bf16(c[nt], al, bh);
            }
        }
        __syncthreads();
    }
    int r0 = blockRow + m0;
    int r1 = r0 + 8;
    float ds0 = 0.f, dd0 = 0.f, ds1 = 0.f, dd1 = 0.f;
#pragma unroll
    for (int nt = 0; nt < 16; nt++) {
        int col = nt * 8 + qid * 2;
        float w0 = sAs[col], w1 = sAs[col + 1];
        float u0 = sAd[col], u1 = sAd[col + 1];
        ds0 += c[nt][0] * w0 + c[nt][1] * w1;
        dd0 += c[nt][0] * u0 + c[nt][1] * u1;
        ds1 += c[nt][2] * w0 + c[nt][3] * w1;
        dd1 += c[nt][2] * u0 + c[nt][3] * u1;
        if (r0 < NN) {
            float2 v0 = make_float2(c[nt][0], c[nt][1]);
            *(float2*)&g_buf0[(size_t)r0 * 128 + col] = v0;
        }
        if (r1 < NN) {
            float2 v1 = make_float2(c[nt][2], c[nt][3]);
            *(float2*)&g_buf0[(size_t)r1 * 128 + col] = v1;
        }
    }
#pragma unroll
    for (int o = 1; o < 4; o <<= 1) {
        ds0 += __shfl_xor_sync(0xffffffffu, ds0, o);
        dd0 += __shfl_xor_sync(0xffffffffu, dd0, o);
        ds1 += __shfl_xor_sync(0xffffffffu, ds1, o);
        dd1 += __shfl_xor_sync(0xffffffffu, dd1, o);
    }
    if (qid == 0) {
        if (r0 < NN) { g_as[r0] = ds0; g_ad[r0] = dd0; }
        if (r1 < NN) { g_as[r1] = ds1; g_ad[r1] = dd1; }
    }
}

__global__ void hist_kernel(const int* __restrict__ edges) {
    int i = blockIdx.x * blockDim.x + threadIdx.x;
    if (i < EE) {
        int d = edge_dst(edges, i);
        if ((unsigned)d < (unsigned)NN) atomicAdd(&g_cnt[d], 1);
    }
}

__global__ void scan1_kernel() {
    __shared__ int sh[1024];
    int i = blockIdx.x * 1024 + threadIdx.x;
    int v = (i < NN) ? g_cnt[i] : 0;
    sh[threadIdx.x] = v;
    __syncthreads();
    for (int off = 1; off < 1024; off <<= 1) {
        int t = (threadIdx.x >= off) ? sh[threadIdx.x - off] : 0;
        __syncthreads();
        sh[threadIdx.x] += t;
        __syncthreads();
    }
    if (i < NN) g_rs[i] = sh[threadIdx.x];          // inclusive, fixed up later
    if (threadIdx.x == 1023) g_csum[blockIdx.x] = sh[1023];
}

__global__ void scan2_kernel(int nchunks) {
    if (threadIdx.x == 0 && blockIdx.x == 0) {
        int run = 0;
        for (int c = 0; c < nchunks; c++) { g_coff[c] = run; run += g_csum[c]; }
        g_asmax_bits = 0u;   // reset for layer-0 asmax
    }
}

__global__ void scan3_kernel() {
    int i = blockIdx.x * blockDim.x + threadIdx.x;
    if (i < NN) g_rs[i] = g_rs[i] - g_cnt[i] + g_coff[i >> 10];  // exclusive start
}

__global__ void scatter_kernel(const int* __restrict__ edges) {
    int i = blockIdx.x * blockDim.x + threadIdx.x;
    if (i < EE) {
        int s = edge_src(edges, i);
        int d = edge_dst(edges, i);
        if ((unsigned)d < (unsigned)NN && (unsigned)s < (unsigned)NN) {
            int pos = g_rs[d] + atomicAdd(&g_fill[d], 1);
            if ((unsigned)pos < (unsigned)EE) g_csr[pos] = s;
        }
    }
}

// global max of g_as (order-invariant -> deterministic)
__global__ void asmax_kernel() {
    int i = blockIdx.x * blockDim.x + threadIdx.x;
    float v = (i < NN) ? g_as[i] : -INFINITY;
#pragma unroll
    for (int o = 16; o; o >>= 1) v = fmaxf(v, __shfl_xor_sync(0xffffffffu, v, o));
    __shared__ float sm[32];
    int lane = threadIdx.x & 31, w = threadIdx.x >> 5;
    if (lane == 0) sm[w] = v;
    __syncthreads();
    if (w == 0) {
        v = (lane < (blockDim.x >> 5)) ? sm[lane] : -INFINITY;
#pragma unroll
        for (int o = 16; o; o >>= 1) v = fmaxf(v, __shfl_xor_sync(0xffffffffu, v, o));
        if (lane == 0) atomicMax(&g_asmax_bits, fkey(v));
    }
}

// ---------------- layer-1 GEMM: fp32 f32x2 path (K=128), fused alpha ----------------
__global__ void __launch_bounds__(256)
gemm1_kernel(const float* __restrict__ W,
             const float* __restrict__ gam, const float* __restrict__ bet,
             const float* __restrict__ a_s, const float* __restrict__ a_d) {
    const float* A = (const float*)g_buf1;
    __shared__ float As[16][128];
    __shared__ float Bs[16][128];
    int tid = threadIdx.x;
    int lane = tid & 31;
    int blockRow = blockIdx.x * 128;
    int tm = (tid >> 4) << 3;
    int tn = (tid & 15) << 3;
    unsigned long long acc[8][4];
#pragma unroll
    for (int i = 0; i < 8; i++)
#pragma unroll
        for (int j = 0; j < 4; j++) acc[i][j] = 0ull;

    for (int k0 = 0; k0 < HH; k0 += 16) {
#pragma unroll
        for (int i = 0; i < 2; i++) {
            int f = tid + i * 256;
            int r = f >> 2, kq = (f & 3) << 2;
            int row = blockRow + r;
            float4 v = make_float4(0.f, 0.f, 0.f, 0.f);
            if (row < NN) {
                v = __ldg((const float4*)&A[(size_t)row * HH + k0 + kq]);
                float4 m4 = *(const float4*)&g_mu[k0 + kq];
                float4 i4 = *(const float4*)&g_istd[k0 + kq];
                float4 g4 = __ldg((const float4*)&gam[k0 + kq]);
                float4 b4 = __ldg((const float4*)&bet[k0 + kq]);
                v.x = bnlrelu(v.x, m4.x, i4.x, g4.x, b4.x);
                v.y = bnlrelu(v.y, m4.y, i4.y, g4.y, b4.y);
                v.z = bnlrelu(v.z, m4.z, i4.z, g4.z, b4.z);
                v.w = bnlrelu(v.w, m4.w, i4.w, g4.w, b4.w);
            }
            As[kq + 0][r] = v.x; As[kq + 1][r] = v.y;
            As[kq + 2][r] = v.z; As[kq + 3][r] = v.w;
        }
#pragma unroll
        for (int i = 0; i < 2; i++) {
            int f = tid + i * 256;
            int kr = f >> 5, c4 = (f & 31) << 2;
            float4 v = __ldg((const float4*)&W[(size_t)(k0 + kr) * 128 + c4]);
            *(float4*)&Bs[kr][c4] = v;
        }
        __syncthreads();
#pragma unroll
        for (int kk = 0; kk < 16; kk++) {
            float4 a0 = *(const float4*)&As[kk][tm];
            float4 a1 = *(const float4*)&As[kk][tm + 4];
            float4 b0 = *(const float4*)&Bs[kk][tn];
            float4 b1 = *(const float4*)&Bs[kk][tn + 4];
            unsigned long long bp[4] = {pack2(b0.x, b0.y), pack2(b0.z, b0.w),
                                        pack2(b1.x, b1.y), pack2(b1.z, b1.w)};
            float av[8] = {a0.x, a0.y, a0.z, a0.w, a1.x, a1.y, a1.z, a1.w};
#pragma unroll
            for (int i = 0; i < 8; i++) {
                unsigned long long aa = pack2(av[i], av[i]);
#pragma unroll
                for (int j = 0; j < 4; j++) acc[i][j] = fma2(aa, bp[j], acc[i][j]);
            }
        }
        __syncthreads();
    }
    float4 as0 = __ldg((const float4*)&a_s[tn]);
    float4 as1 = __ldg((const float4*)&a_s[tn + 4]);
    float4 ad0 = __ldg((const float4*)&a_d[tn]);
    float4 ad1 = __ldg((const float4*)&a_d[tn + 4]);
#pragma unroll
    for (int i = 0; i < 8; i++) {
        int row = blockRow + tm + i;
        float2 f0 = *(float2*)&acc[i][0];
        float2 f1 = *(float2*)&acc[i][1];
        float2 f2 = *(float2*)&acc[i][2];
        float2 f3 = *(float2*)&acc[i][3];
        float dsv = f0.x * as0.x + f0.y * as0.y + f1.x * as0.z + f1.y * as0.w
                  + f2.x * as1.x + f2.y * as1.y + f3.x * as1.z + f3.y * as1.w;
        float ddv = f0.x * ad0.x + f0.y * ad0.y + f1.x * ad0.z + f1.y * ad0.w
                  + f2.x * ad1.x + f2.y * ad1.y + f3.x * ad1.z + f3.y * ad1.w;
#pragma unroll
        for (int o = 1; o < 16; o <<= 1) {
            dsv += __shfl_xor_sync(0xffffffffu, dsv, o);
            ddv += __shfl_xor_sync(0xffffffffu, ddv, o);
        }
        if (row < NN) {
            unsigned long long* cp = (unsigned long long*)&g_buf0[(size_t)row * 128 + tn];
#pragma unroll
            for (int j = 0; j < 4; j++) cp[j] = acc[i][j];
            if ((lane & 15) == 0) { g_as[row] = dsv; g_ad[row] = ddv; }
        }
    }
}

// GAT softmax-aggregate via CSR, warp per dst node: g_buf0 -> g_buf1
// Single pass: M_d = leaky(global_max(as) + ad[d]) >= all edge logits (leaky monotone).
__global__ void aggregate_kernel() {
    int lane = threadIdx.x & 31;
    int warp = (blockIdx.x * blockDim.x + threadIdx.x) >> 5;
    int nw = (gridDim.x * blockDim.x) >> 5;
    const float4* h2v = (const float4*)g_buf0;
    float amax = funkey(g_asmax_bits);
    for (int d = warp; d < NN; d += nw) {
        int deg = g_cnt[d];
        int st = g_rs[d];
        float ad = g_ad[d];
        float ebound = amax + ad;
        float mx = ebound > 0.f ? ebound : 0.2f * ebound;
        float4 acc = make_float4(0.f, 0.f, 0.f, 0.f);
        float dsum = 0.f;
        for (int base = 0; base < deg; base += 32) {
            int nch = min(32, deg - base);
            int s_my = 0; float w_my = 0.f;
            if (lane < nch) {
                s_my = g_csr[st + base + lane];
                float e = g_as[s_my] + ad;
                e = e > 0.f ? e : 0.2f * e;
                w_my = __expf(e - mx);
                dsum += w_my;
            }
            int j = 0;
            for (; j + 3 < nch; j += 4) {
                int s0 = __shfl_sync(0xffffffffu, s_my, j);
                int s1 = __shfl_sync(0xffffffffu, s_my, j + 1);
                int s2 = __shfl_sync(0xffffffffu, s_my, j + 2);
                int s3 = __shfl_sync(0xffffffffu, s_my, j + 3);
                float w0 = __shfl_sync(0xffffffffu, w_my, j);
                float w1 = __shfl_sync(0xffffffffu, w_my, j + 1);
                float w2 = __shfl_sync(0xffffffffu, w_my, j + 2);
                float w3 = __shfl_sync(0xffffffffu, w_my, j + 3);
                float4 v0 = __ldg(&h2v[(size_t)s0 * 32 + lane]);
                float4 v1 = __ldg(&h2v[(size_t)s1 * 32 + lane]);
                float4 v2 = __ldg(&h2v[(size_t)s2 * 32 + lane]);
                float4 v3 = __ldg(&h2v[(size_t)s3 * 32 + lane]);
                acc.x = fmaf(w0, v0.x, acc.x); acc.y = fmaf(w0, v0.y, acc.y);
                acc.z = fmaf(w0, v0.z, acc.z); acc.w = fmaf(w0, v0.w, acc.w);
                acc.x = fmaf(w1, v1.x, acc.x); acc.y = fmaf(w1, v1.y, acc.y);
                acc.z = fmaf(w1, v1.z, acc.z); acc.w = fmaf(w1, v1.w, acc.w);
                acc.x = fmaf(w2, v2.x, acc.x); acc.y = fmaf(w2, v2.y, acc.y);
                acc.z = fmaf(w2, v2.z, acc.z); acc.w = fmaf(w2, v2.w, acc.w);
                acc.x = fmaf(w3, v3.x, acc.x); acc.y = fmaf(w3, v3.y, acc.y);
                acc.z = fmaf(w3, v3.z, acc.z); acc.w = fmaf(w3, v3.w, acc.w);
            }
            for (; j < nch; j++) {
                int s = __shfl_sync(0xffffffffu, s_my, j);
                float w = __shfl_sync(0xffffffffu, w_my, j);
                float4 v = __ldg(&h2v[(size_t)s * 32 + lane]);
                acc.x = fmaf(w, v.x, acc.x); acc.y = fmaf(w, v.y, acc.y);
                acc.z = fmaf(w, v.z, acc.z); acc.w = fmaf(w, v.w, acc.w);
            }
        }
#pragma unroll
        for (int o = 16; o; o >>= 1) dsum += __shfl_xor_sync(0xffffffffu, dsum, o);
        float inv = 1.0f / (dsum + 1e-16f);
        acc.x *= inv; acc.y *= inv; acc.z *= inv; acc.w *= inv;
        ((float4*)g_buf1)[(size_t)d * 32 + lane] = acc;
    }
}

// BN stats on g_buf1: single read pass (sum + sumsq), deterministic partials
__global__ void bn_stats_kernel() {
    int c = threadIdx.x;  // 128
    float s = 0.f, q = 0.f;
    for (int r = blockIdx.x; r < NN; r += gridDim.x) {
        float v = g_buf1[(size_t)r * 128 + c];
        s += v;
        q = fmaf(v, v, q);
    }
    g_part[blockIdx.x * 128 + c] = s;
    g_part2[blockIdx.x * 128 + c] = q;
}
__global__ void bn_finalize_kernel() {
    int c = threadIdx.x;
    float s = 0.f, q = 0.f;
    for (int p = 0; p < BNP; p++) {
        s += g_part[p * 128 + c];
        q += g_part2[p * 128 + c];
    }
    float mu = s / (float)NN;
    float var = q / (float)NN - mu * mu;
    var = var > 0.f ? var : 0.f;
    g_mu[c] = mu;
    g_istd[c] = rsqrtf(var + 1e-5f);
    if (c == 0) g_asmax_bits = 0u;   // reset for next layer's asmax
}

// heads on g_buf1
__global__ void __launch_bounds__(256)
heads_kernel(const float* __restrict__ gam, const float* __restrict__ bet,
             const float* __restrict__ locW, const float* __restrict__ locb,
             const float* __restrict__ stdW, const float* __restrict__ stdb,
             float* __restrict__ out_loc, float* __restrict__ out_std) {
    __shared__ float sL[128 * 32];
    __shared__ float sS[128 * 32];
    for (int i = threadIdx.x; i < 4096; i += 256) { sL[i] = locW[i]; sS[i] = stdW[i]; }
    __syncthreads();
    int lane = threadIdx.x & 31;
    int warp = (blockIdx.x * blockDim.x + threadIdx.x) >> 5;
    int nw = (gridDim.x * blockDim.x) >> 5;
    float4 m4 = *(const float4*)&g_mu[lane * 4];
    float4 i4 = *(const float4*)&g_istd[lane * 4];
    float4 g4 = __ldg((const float4*)&gam[lane * 4]);
    float4 b4 = __ldg((const float4*)&bet[lane * 4]);
    float lb = __ldg(&locb[lane]);
    float sb = __ldg(&stdb[lane]);
    for (int r = warp; r < NN; r += nw) {
        float4 v = *(const float4*)&g_buf1[(size_t)r * 128 + lane * 4];
        float vr[4];
        vr[0] = bnlrelu(v.x, m4.x, i4.x, g4.x, b4.x);
        vr[1] = bnlrelu(v.y, m4.y, i4.y, g4.y, b4.y);
        vr[2] = bnlrelu(v.z, m4.z, i4.z, g4.z, b4.z);
        vr[3] = bnlrelu(v.w, m4.w, i4.w, g4.w, b4.w);
        float al = 0.f, as = 0.f;
#pragma unroll
        for (int k4 = 0; k4 < 32; k4++) {
#pragma unroll
            for (int q = 0; q < 4; q++) {
                float vk = __shfl_sync(0xffffffffu, vr[q], k4);
                int k = k4 * 4 + q;
                al = fmaf(vk, sL[k * 32 + lane], al);
                as = fmaf(vk, sS[k * 32 + lane], as);
            }
        }
        out_loc[(size_t)r * 32 + lane] = al + lb;
        float z = as + sb;
        float sp = (z > 0.f) ? z + log1pf(__expf(-z)) : log1pf(__expf(z));
        out_std[(size_t)r * 32 + lane] = sp + 1e-7f;
    }
}

// ---------------- launch ----------------
extern "C" void kernel_launch(void* const* d_in, const int* in_sizes, int n_in,
                              void* d_out, int out_size) {
    const float* x = (const float*)d_in[0];
    const int* edges = (const int*)d_in[1];
    const float* W0 = (const float*)d_in[2];
    const float* a_s0 = (const float*)d_in[3];
    const float* a_d0 = (const float*)d_in[4];
    const float* g0 = (const float*)d_in[5];
    const float* b0 = (const float*)d_in[6];
    const float* W1 = (const float*)d_in[7];
    const float* a_s1 = (const float*)d_in[8];
    const float* a_d1 = (const float*)d_in[9];
    const float* g1 = (const float*)d_in[10];
    const float* b1 = (const float*)d_in[11];
    const float* locW = (const float*)d_in[12];
    const float* locb = (const float*)d_in[13];
    const float* stdW = (const float*)d_in[14];
    const float* stdb = (const float*)d_in[15];

    float* out = (float*)d_out;
    float* out_loc = out;
    float* out_std = out + (size_t)NN * NOUT;
    float* out_l = out + 2 * (size_t)NN * NOUT;

    const int CH = (NN + 1023) / 1024;  // 98

    // launch order puts gemm0 in the ncu-profiled slot (#4)
    detect_kernel<<<1, 32>>>(edges);
    zero_int2_kernel<<<(NN + 255) / 256, 256>>>();
    w0prep_kernel<<<256, 256>>>(W0);
    gemm0_bf16x2_kernel<<<(NN + 127) / 128, 256>>>(x, out_l, a_s0, a_d0);

    // CSR build
    hist_kernel<<<(EE + 255) / 256, 256>>>(edges);
    scan1_kernel<<<CH, 1024>>>();
    scan2_kernel<<<1, 32>>>(CH);   // also resets asmax
    scan3_kernel<<<(NN + 255) / 256, 256>>>();
    scatter_kernel<<<(EE + 255) / 256, 256>>>(edges);

    // ---- layer 0 ----
    asmax_kernel<<<CH, 1024>>>();
    aggregate_kernel<<<12500, 256>>>();
    bn_stats_kernel<<<BNP, 128>>>();
    bn_finalize_kernel<<<1, 128>>>();  // also resets asmax

    // ---- layer 1 ----
    gemm1_kernel<<<(NN + 127) / 128, 256>>>(W1, g0, b0, a_s1, a_d1);
    asmax_kernel<<<CH, 1024>>>();
    aggregate_kernel<<<12500, 256>>>();
    bn_stats_kernel<<<BNP, 128>>>();
    bn_finalize_kernel<<<1, 128>>>();

    // ---- heads ----
    heads_kernel<<<2048, 256>>>(g1, b1, locW, locb, stdW, stdb, out_loc, out_std);
}

// round 17
// speedup vs baseline: 1.1770x; 1.1074x over previous
#include <cuda_runtime.h>
#include <cuda_bf16.h>
#include <math.h>

#define NN 100000
#define EE 1600000
#define FIN 1024
#define HH 128
#define NOUT 32
#define BNP 1024

// ---------------- scratch (static __device__, referenced only from device code) ----------------
__device__ float g_scale[NN];
__device__ float g_buf0[(size_t)NN * HH];   // GEMM output h2
__device__ float g_buf1[(size_t)NN * HH];   // aggregate output
__device__ float g_as[NN], g_ad[NN];
__device__ int   g_cnt[NN], g_rs[NN], g_fill[NN];
__device__ int   g_csr[EE];
__device__ int   g_csum[128], g_coff[128];
__device__ float g_mu[HH], g_istd[HH];
__device__ float g_part[BNP * HH];
__device__ float g_part2[BNP * HH];
__device__ unsigned g_W0hi[512 * 128];      // W0 bf16 hi, [kpair][n]
__device__ unsigned g_W0lo[512 * 128];      // W0 bf16 lo
__device__ int   g_is64;            // 1 if edge_index is int64, 0 if int32
__device__ unsigned g_asmax_bits;   // order-invariant float max encoding

// ---------------- helpers ----------------
__device__ __forceinline__ unsigned long long pack2(float lo, float hi) {
    unsigned long long r;
    asm("mov.b64 %0, {%1, %2};" : "=l"(r) : "f"(lo), "f"(hi));
    return r;
}
__device__ __forceinline__ unsigned long long fma2(unsigned long long a,
                                                   unsigned long long b,
                                                   unsigned long long c) {
    asm("fma.rn.f32x2 %0, %1, %2, %3;" : "=l"(c) : "l"(a), "l"(b), "l"(c));
    return c;
}
__device__ __forceinline__ float bnlrelu(float v, float m, float is, float g, float b) {
    float t = (v - m) * is * g + b;
    return t > 0.f ? t : 0.2f * t;
}
__device__ __forceinline__ unsigned fkey(float f) {
    unsigned b = __float_as_uint(f);
    return (b & 0x80000000u) ? ~b : (b | 0x80000000u);
}
__device__ __forceinline__ float funkey(unsigned k) {
    unsigned b = (k & 0x80000000u) ? (k & 0x7fffffffu) : ~k;
    return __uint_as_float(b);
}
// split (even,odd) pair into bf16 hi/lo packed words (even in low 16 bits)
__device__ __forceinline__ void split_pack(float e, float o, unsigned& hi, unsigned& lo) {
    __nv_bfloat162 hp = __float22bfloat162_rn(make_float2(e, o));   // 1 cvt
    float he = __bfloat162float(__low2bfloat16(hp));                // shift
    float ho = __bfloat162float(__high2bfloat16(hp));
    __nv_bfloat162 lp = __float22bfloat162_rn(make_float2(e - he, o - ho));
    hi = *reinterpret_cast<unsigned*>(&hp);
    lo = *reinterpret_cast<unsigned*>(&lp);
}
__device__ __forceinline__ void mma_bf16(float c[4], const unsigned a[4], const unsigned b[2]) {
    asm volatile(
        "mma.sync.aligned.m16n8k16.row.col.f32.bf16.bf16.f32 "
        "{%0,%1,%2,%3}, {%4,%5,%6,%7}, {%8,%9}, {%0,%1,%2,%3};"
        : "+f"(c[0]), "+f"(c[1]), "+f"(c[2]), "+f"(c[3])
        : "r"(a[0]), "r"(a[1]), "r"(a[2]), "r"(a[3]), "r"(b[0]), "r"(b[1]));
}
// edge accessors: e is the raw buffer as int32 words
__device__ __forceinline__ int edge_src(const int* e, int i) {
    return g_is64 ? (int)((const long long*)e)[i] : e[i];
}
__device__ __forceinline__ int edge_dst(const int* e, int i) {
    return g_is64 ? (int)((const long long*)e)[EE + i] : e[EE + i];
}

// ---------------- kernels ----------------
__global__ void detect_kernel(const int* __restrict__ e) {
    if (threadIdx.x == 0 && blockIdx.x == 0) {
        int z = 0;
#pragma unroll
        for (int k = 1; k <= 15; k += 2) z |= e[k];   // high words if int64
        g_is64 = (z == 0) ? 1 : 0;
    }
}

__global__ void zero_int2_kernel() {
    int i = blockIdx.x * blockDim.x + threadIdx.x;
    if (i < NN) { g_cnt[i] = 0; g_fill[i] = 0; }
}

// row sums of x -> l output + scale = 10000/l (standalone: full occupancy, high MLP)
__global__ void rowsum_kernel(const float* __restrict__ x, float* __restrict__ out_l) {
    int lane = threadIdx.x & 31;
    int warp = (blockIdx.x * blockDim.x + threadIdx.x) >> 5;
    int nw = (gridDim.x * blockDim.x) >> 5;
    const float4* xv = (const float4*)x;
    for (int r = warp; r < NN; r += nw) {
        float s = 0.f;
        size_t base = (size_t)r * 256;
#pragma unroll
        for (int i = 0; i < 8; i++) {
            float4 v = __ldg(&xv[base + lane + i * 32]);
            s += v.x + v.y + v.z + v.w;
        }
#pragma unroll
        for (int o = 16; o; o >>= 1) s += __shfl_xor_sync(0xffffffffu, s, o);
        if (lane == 0) { out_l[r] = s; g_scale[r] = 10000.0f / s; }
    }
}

// one-time W0 bf16 hi/lo split, laid out [kpair][n] to mirror smem tiles
__global__ void w0prep_kernel(const float* __restrict__ W) {
    int i = blockIdx.x * blockDim.x + threadIdx.x;
    if (i < 512 * 128) {
        int kp = i >> 7, n = i & 127;
        float e = __ldg(&W[(size_t)(2 * kp) * 128 + n]);
        float o = __ldg(&W[(size_t)(2 * kp + 1) * 128 + n]);
        unsigned h, l;
        split_pack(e, o, h, l);
        g_W0hi[i] = h;
        g_W0lo[i] = l;
    }
}

// ---------------- layer-0 GEMM: bf16x2 compensated tensor cores ----------------
// A-stream register double-buffer: next chunk's LDGs overlap current chunk's MMAs.
#define SPITCH 136
__global__ void __launch_bounds__(256, 2)
gemm0_bf16x2_kernel(const float* __restrict__ A,
                    const float* __restrict__ a_s, const float* __restrict__ a_d) {
    __shared__ unsigned As_hi[16 * SPITCH];
    __shared__ unsigned As_lo[16 * SPITCH];
    __shared__ unsigned Bs_hi[16 * SPITCH];
    __shared__ unsigned Bs_lo[16 * SPITCH];
    __shared__ float sc_sh[128];
    __shared__ float sAs[128], sAd[128];
    int tid = threadIdx.x;
    int lane = tid & 31;
    int warpId = tid >> 5;
    int blockRow = blockIdx.x * 128;
    int grp = lane >> 2;        // 0..7
    int qid = lane & 3;         // 0..3
    int m0 = warpId * 16 + grp;

    if (tid < 128) {
        sAs[tid] = __ldg(&a_s[tid]);
        sAd[tid] = __ldg(&a_d[tid]);
        int row = blockRow + tid;
        sc_sh[tid] = (row < NN) ? g_scale[row] : 0.f;
    }

    float c[16][4];
#pragma unroll
    for (int nt = 0; nt < 16; nt++)
#pragma unroll
        for (int j = 0; j < 4; j++) c[nt][j] = 0.f;

    // A prefetch registers (chunk 0)
    float4 pre[4];
#pragma unroll
    for (int i = 0; i < 4; i++) {
        int f = tid + i * 256;
        int r = f >> 3;
        int kq = (f & 7) << 2;
        int row = blockRow + r;
        pre[i] = (row < NN) ? __ldg((const float4*)&A[(size_t)row * FIN + kq])
                            : make_float4(0.f, 0.f, 0.f, 0.f);
    }
    __syncthreads();   // sc_sh ready

    for (int k0 = 0; k0 < FIN; k0 += 32) {
        // process prefetched A chunk -> smem (x >= 0 so log(1+x) is safe; OOB rows: 0*0+1 -> log=0)
#pragma unroll
        for (int i = 0; i < 4; i++) {
            int f = tid + i * 256;
            int r = f >> 3;
            int kq = (f & 7) << 2;
            float sc = sc_sh[r];
            float4 v = pre[i];
            v.x = __logf(fmaf(v.x, sc, 1.0f));
            v.y = __logf(fmaf(v.y, sc, 1.0f));
            v.z = __logf(fmaf(v.z, sc, 1.0f));
            v.w = __logf(fmaf(v.w, sc, 1.0f));
            unsigned h0, l0, h1, l1;
            split_pack(v.x, v.y, h0, l0);
            split_pack(v.z, v.w, h1, l1);
            int kp = kq >> 1;
            As_hi[(kp + 0) * SPITCH + r] = h0;
            As_lo[(kp + 0) * SPITCH + r] = l0;
            As_hi[(kp + 1) * SPITCH + r] = h1;
            As_lo[(kp + 1) * SPITCH + r] = l1;
        }
        // B chunk: pre-split W0 (L2-resident), plain uint4 copies
        {
            int kbase = (k0 >> 1) * 128;
#pragma unroll
            for (int i = 0; i < 2; i++) {
                int f = tid + i * 256;      // 0..511
                int kp = f >> 5;            // 0..15
                int n4 = (f & 31) << 2;     // 0..124
                uint4 h = *(const uint4*)&g_W0hi[kbase + kp * 128 + n4];
                uint4 l = *(const uint4*)&g_W0lo[kbase + kp * 128 + n4];
                Bs_hi[kp * SPITCH + n4 + 0] = h.x; Bs_lo[kp * SPITCH + n4 + 0] = l.x;
                Bs_hi[kp * SPITCH + n4 + 1] = h.y; Bs_lo[kp * SPITCH + n4 + 1] = l.y;
                Bs_hi[kp * SPITCH + n4 + 2] = h.z; Bs_lo[kp * SPITCH + n4 + 2] = l.z;
                Bs_hi[kp * SPITCH + n4 + 3] = h.w; Bs_lo[kp * SPITCH + n4 + 3] = l.w;
            }
        }
        // prefetch NEXT A chunk (DRAM latency hidden under the MMA phase below)
        if (k0 + 32 < FIN) {
#pragma unroll
            for (int i = 0; i < 4; i++) {
                int f = tid + i * 256;
                int r = f >> 3;
                int kq = (f & 7) << 2;
                int row = blockRow + r;
                pre[i] = (row < NN)
                    ? __ldg((const float4*)&A[(size_t)row * FIN + k0 + 32 + kq])
                    : make_float4(0.f, 0.f, 0.f, 0.f);
            }
        }
        __syncthreads();   // tiles ready
#pragma unroll
        for (int kk = 0; kk < 2; kk++) {
            int kpb = kk * 8;
            unsigned ah[4], al[4];
            ah[0] = As_hi[(kpb + qid) * SPITCH + m0];
            ah[1] = As_hi[(kpb + qid) * SPITCH + m0 + 8];
            ah[2] = As_hi[(kpb + qid + 4) * SPITCH + m0];
            ah[3] = As_hi[(kpb + qid + 4) * SPITCH + m0 + 8];
            al[0] = As_lo[(kpb + qid) * SPITCH + m0];
            al[1] = As_lo[(kpb + qid) * SPITCH + m0 + 8];
            al[2] = As_lo[(kpb + qid + 4) * SPITCH + m0];
            al[3] = As_lo[(kpb + qid + 4) * SPITCH + m0 + 8];
#pragma unroll
            for (int nt = 0; nt < 16; nt++) {
                int nb = nt * 8 + grp;
                unsigned bh[2], bl[2];
                bh[0] = Bs_hi[(kpb + qid) * SPITCH + nb];
                bh[1] = Bs_hi[(kpb + qid + 4) * SPITCH + nb];
                bl[0] = Bs_lo[(kpb + qid) * SPITCH + nb];
                bl[1] = Bs_lo[(kpb + qid + 4) * SPITCH + nb];
                mma_bf16(c[nt], ah, bh);
                mma_bf16(c[nt], ah, bl);
                mma_bf16(c[nt], al, bh);
            }
        }
        __syncthreads();   // MMA done before smem overwrite next iter
    }
    int r0 = blockRow + m0;
    int r1 = r0 + 8;
    float ds0 = 0.f, dd0 = 0.f, ds1 = 0.f, dd1 = 0.f;
#pragma unroll
    for (int nt = 0; nt < 16; nt++) {
        int col = nt * 8 + qid * 2;
        float w0 = sAs[col], w1 = sAs[col + 1];
        float u0 = sAd[col], u1 = sAd[col + 1];
        ds0 += c[nt][0] * w0 + c[nt][1] * w1;
        dd0 += c[nt][0] * u0 + c[nt][1] * u1;
        ds1 += c[nt][2] * w0 + c[nt][3] * w1;
        dd1 += c[nt][2] * u0 + c[nt][3] * u1;
        if (r0 < NN) {
            float2 v0 = make_float2(c[nt][0], c[nt][1]);
            *(float2*)&g_buf0[(size_t)r0 * 128 + col] = v0;
        }
        if (r1 < NN) {
            float2 v1 = make_float2(c[nt][2], c[nt][3]);
            *(float2*)&g_buf0[(size_t)r1 * 128 + col] = v1;
        }
    }
#pragma unroll
    for (int o = 1; o < 4; o <<= 1) {
        ds0 += __shfl_xor_sync(0xffffffffu, ds0, o);
        dd0 += __shfl_xor_sync(0xffffffffu, dd0, o);
        ds1 += __shfl_xor_sync(0xffffffffu, ds1, o);
        dd1 += __shfl_xor_sync(0xffffffffu, dd1, o);
    }
    if (qid == 0) {
        if (r0 < NN) { g_as[r0] = ds0; g_ad[r0] = dd0; }
        if (r1 < NN) { g_as[r1] = ds1; g_ad[r1] = dd1; }
    }
}

__global__ void hist_kernel(const int* __restrict__ edges) {
    int i = blockIdx.x * blockDim.x + threadIdx.x;
    if (i < EE) {
        int d = edge_dst(edges, i);
        if ((unsigned)d < (unsigned)NN) atomicAdd(&g_cnt[d], 1);
    }
}

__global__ void scan1_kernel() {
    __shared__ int sh[1024];
    int i = blockIdx.x * 1024 + threadIdx.x;
    int v = (i < NN) ? g_cnt[i] : 0;
    sh[threadIdx.x] = v;
    __syncthreads();
    for (int off = 1; off < 1024; off <<= 1) {
        int t = (threadIdx.x >= off) ? sh[threadIdx.x - off] : 0;
        __syncthreads();
        sh[threadIdx.x] += t;
        __syncthreads();
    }
    if (i < NN) g_rs[i] = sh[threadIdx.x];          // inclusive, fixed up later
    if (threadIdx.x == 1023) g_csum[blockIdx.x] = sh[1023];
}

__global__ void scan2_kernel(int nchunks) {
    if (threadIdx.x == 0 && blockIdx.x == 0) {
        int run = 0;
        for (int c = 0; c < nchunks; c++) { g_coff[c] = run; run += g_csum[c]; }
        g_asmax_bits = 0u;   // reset for layer-0 asmax
    }
}

__global__ void scan3_kernel() {
    int i = blockIdx.x * blockDim.x + threadIdx.x;
    if (i < NN) g_rs[i] = g_rs[i] - g_cnt[i] + g_coff[i >> 10];  // exclusive start
}

__global__ void scatter_kernel(const int* __restrict__ edges) {
    int i = blockIdx.x * blockDim.x + threadIdx.x;
    if (i < EE) {
        int s = edge_src(edges, i);
        int d = edge_dst(edges, i);
        if ((unsigned)d < (unsigned)NN && (unsigned)s < (unsigned)NN) {
            int pos = g_rs[d] + atomicAdd(&g_fill[d], 1);
            if ((unsigned)pos < (unsigned)EE) g_csr[pos] = s;
        }
    }
}

// global max of g_as (order-invariant -> deterministic)
__global__ void asmax_kernel() {
    int i = blockIdx.x * blockDim.x + threadIdx.x;
    float v = (i < NN) ? g_as[i] : -INFINITY;
#pragma unroll
    for (int o = 16; o; o >>= 1) v = fmaxf(v, __shfl_xor_sync(0xffffffffu, v, o));
    __shared__ float sm[32];
    int lane = threadIdx.x & 31, w = threadIdx.x >> 5;
    if (lane == 0) sm[w] = v;
    __syncthreads();
    if (w == 0) {
        v = (lane < (blockDim.x >> 5)) ? sm[lane] : -INFINITY;
#pragma unroll
        for (int o = 16; o; o >>= 1) v = fmaxf(v, __shfl_xor_sync(0xffffffffu, v, o));
        if (lane == 0) atomicMax(&g_asmax_bits, fkey(v));
    }
}

// ---------------- layer-1 GEMM: fp32 f32x2 path (K=128), fused alpha ----------------
__global__ void __launch_bounds__(256)
gemm1_kernel(const float* __restrict__ W,
             const float* __restrict__ gam, const float* __restrict__ bet,
             const float* __restrict__ a_s, const float* __restrict__ a_d) {
    const float* A = (const float*)g_buf1;
    __shared__ float As[16][128];
    __shared__ float Bs[16][128];
    int tid = threadIdx.x;
    int lane = tid & 31;
    int blockRow = blockIdx.x * 128;
    int tm = (tid >> 4) << 3;
    int tn = (tid & 15) << 3;
    unsigned long long acc[8][4];
#pragma unroll
    for (int i = 0; i < 8; i++)
#pragma unroll
        for (int j = 0; j < 4; j++) acc[i][j] = 0ull;

    for (int k0 = 0; k0 < HH; k0 += 16) {
#pragma unroll
        for (int i = 0; i < 2; i++) {
            int f = tid + i * 256;
            int r = f >> 2, kq = (f & 3) << 2;
            int row = blockRow + r;
            float4 v = make_float4(0.f, 0.f, 0.f, 0.f);
            if (row < NN) {
                v = __ldg((const float4*)&A[(size_t)row * HH + k0 + kq]);
                float4 m4 = *(const float4*)&g_mu[k0 + kq];
                float4 i4 = *(const float4*)&g_istd[k0 + kq];
                float4 g4 = __ldg((const float4*)&gam[k0 + kq]);
                float4 b4 = __ldg((const float4*)&bet[k0 + kq]);
                v.x = bnlrelu(v.x, m4.x, i4.x, g4.x, b4.x);
                v.y = bnlrelu(v.y, m4.y, i4.y, g4.y, b4.y);
                v.z = bnlrelu(v.z, m4.z, i4.z, g4.z, b4.z);
                v.w = bnlrelu(v.w, m4.w, i4.w, g4.w, b4.w);
            }
            As[kq + 0][r] = v.x; As[kq + 1][r] = v.y;
            As[kq + 2][r] = v.z; As[kq + 3][r] = v.w;
        }
#pragma unroll
        for (int i = 0; i < 2; i++) {
            int f = tid + i * 256;
            int kr = f >> 5, c4 = (f & 31) << 2;
            float4 v = __ldg((const float4*)&W[(size_t)(k0 + kr) * 128 + c4]);
            *(float4*)&Bs[kr][c4] = v;
        }
        __syncthreads();
#pragma unroll
        for (int kk = 0; kk < 16; kk++) {
            float4 a0 = *(const float4*)&As[kk][tm];
            float4 a1 = *(const float4*)&As[kk][tm + 4];
            float4 b0 = *(const float4*)&Bs[kk][tn];
            float4 b1 = *(const float4*)&Bs[kk][tn + 4];
            unsigned long long bp[4] = {pack2(b0.x, b0.y), pack2(b0.z, b0.w),
                                        pack2(b1.x, b1.y), pack2(b1.z, b1.w)};
            float av[8] = {a0.x, a0.y, a0.z, a0.w, a1.x, a1.y, a1.z, a1.w};
#pragma unroll
            for (int i = 0; i < 8; i++) {
                unsigned long long aa = pack2(av[i], av[i]);
#pragma unroll
                for (int j = 0; j < 4; j++) acc[i][j] = fma2(aa, bp[j], acc[i][j]);
            }
        }
        __syncthreads();
    }
    float4 as0 = __ldg((const float4*)&a_s[tn]);
    float4 as1 = __ldg((const float4*)&a_s[tn + 4]);
    float4 ad0 = __ldg((const float4*)&a_d[tn]);
    float4 ad1 = __ldg((const float4*)&a_d[tn + 4]);
#pragma unroll
    for (int i = 0; i < 8; i++) {
        int row = blockRow + tm + i;
        float2 f0 = *(float2*)&acc[i][0];
        float2 f1 = *(float2*)&acc[i][1];
        float2 f2 = *(float2*)&acc[i][2];
        float2 f3 = *(float2*)&acc[i][3];
        float dsv = f0.x * as0.x + f0.y * as0.y + f1.x * as0.z + f1.y * as0.w
                  + f2.x * as1.x + f2.y * as1.y + f3.x * as1.z + f3.y * as1.w;
        float ddv = f0.x * ad0.x + f0.y * ad0.y + f1.x * ad0.z + f1.y * ad0.w
                  + f2.x * ad1.x + f2.y * ad1.y + f3.x * ad1.z + f3.y * ad1.w;
#pragma unroll
        for (int o = 1; o < 16; o <<= 1) {
            dsv += __shfl_xor_sync(0xffffffffu, dsv, o);
            ddv += __shfl_xor_sync(0xffffffffu, ddv, o);
        }
        if (row < NN) {
            unsigned long long* cp = (unsigned long long*)&g_buf0[(size_t)row * 128 + tn];
#pragma unroll
            for (int j = 0; j < 4; j++) cp[j] = acc[i][j];
            if ((lane & 15) == 0) { g_as[row] = dsv; g_ad[row] = ddv; }
        }
    }
}

// GAT softmax-aggregate via CSR, warp per dst node: g_buf0 -> g_buf1
// Single pass: M_d = leaky(global_max(as) + ad[d]) >= all edge logits (leaky monotone).
__global__ void aggregate_kernel() {
    int lane = threadIdx.x & 31;
    int warp = (blockIdx.x * blockDim.x + threadIdx.x) >> 5;
    int nw = (gridDim.x * blockDim.x) >> 5;
    const float4* h2v = (const float4*)g_buf0;
    float amax = funkey(g_asmax_bits);
    for (int d = warp; d < NN; d += nw) {
        int deg = g_cnt[d];
        int st = g_rs[d];
        float ad = g_ad[d];
        float ebound = amax + ad;
        float mx = ebound > 0.f ? ebound : 0.2f * ebound;
        float4 acc = make_float4(0.f, 0.f, 0.f, 0.f);
        float dsum = 0.f;
        for (int base = 0; base < deg; base += 32) {
            int nch = min(32, deg - base);
            int s_my = 0; float w_my = 0.f;
            if (lane < nch) {
                s_my = g_csr[st + base + lane];
                float e = g_as[s_my] + ad;
                e = e > 0.f ? e : 0.2f * e;
                w_my = __expf(e - mx);
                dsum += w_my;
            }
            int j = 0;
            for (; j + 3 < nch; j += 4) {
                int s0 = __shfl_sync(0xffffffffu, s_my, j);
                int s1 = __shfl_sync(0xffffffffu, s_my, j + 1);
                int s2 = __shfl_sync(0xffffffffu, s_my, j + 2);
                int s3 = __shfl_sync(0xffffffffu, s_my, j + 3);
                float w0 = __shfl_sync(0xffffffffu, w_my, j);
                float w1 = __shfl_sync(0xffffffffu, w_my, j + 1);
                float w2 = __shfl_sync(0xffffffffu, w_my, j + 2);
                float w3 = __shfl_sync(0xffffffffu, w_my, j + 3);
                float4 v0 = __ldg(&h2v[(size_t)s0 * 32 + lane]);
                float4 v1 = __ldg(&h2v[(size_t)s1 * 32 + lane]);
                float4 v2 = __ldg(&h2v[(size_t)s2 * 32 + lane]);
                float4 v3 = __ldg(&h2v[(size_t)s3 * 32 + lane]);
                acc.x = fmaf(w0, v0.x, acc.x); acc.y = fmaf(w0, v0.y, acc.y);
                acc.z = fmaf(w0, v0.z, acc.z); acc.w = fmaf(w0, v0.w, acc.w);
                acc.x = fmaf(w1, v1.x, acc.x); acc.y = fmaf(w1, v1.y, acc.y);
                acc.z = fmaf(w1, v1.z, acc.z); acc.w = fmaf(w1, v1.w, acc.w);
                acc.x = fmaf(w2, v2.x, acc.x); acc.y = fmaf(w2, v2.y, acc.y);
                acc.z = fmaf(w2, v2.z, acc.z); acc.w = fmaf(w2, v2.w, acc.w);
                acc.x = fmaf(w3, v3.x, acc.x); acc.y = fmaf(w3, v3.y, acc.y);
                acc.z = fmaf(w3, v3.z, acc.z); acc.w = fmaf(w3, v3.w, acc.w);
            }
            for (; j < nch; j++) {
                int s = __shfl_sync(0xffffffffu, s_my, j);
                float w = __shfl_sync(0xffffffffu, w_my, j);
                float4 v = __ldg(&h2v[(size_t)s * 32 + lane]);
                acc.x = fmaf(w, v.x, acc.x); acc.y = fmaf(w, v.y, acc.y);
                acc.z = fmaf(w, v.z, acc.z); acc.w = fmaf(w, v.w, acc.w);
            }
        }
#pragma unroll
        for (int o = 16; o; o >>= 1) dsum += __shfl_xor_sync(0xffffffffu, dsum, o);
        float inv = 1.0f / (dsum + 1e-16f);
        acc.x *= inv; acc.y *= inv; acc.z *= inv; acc.w *= inv;
        ((float4*)g_buf1)[(size_t)d * 32 + lane] = acc;
    }
}

// BN stats on g_buf1: single read pass (sum + sumsq), deterministic partials
__global__ void bn_stats_kernel() {
    int c = threadIdx.x;  // 128
    float s = 0.f, q = 0.f;
    for (int r = blockIdx.x; r < NN; r += gridDim.x) {
        float v = g_buf1[(size_t)r * 128 + c];
        s += v;
        q = fmaf(v, v, q);
    }
    g_part[blockIdx.x * 128 + c] = s;
    g_part2[blockIdx.x * 128 + c] = q;
}
__global__ void bn_finalize_kernel() {
    int c = threadIdx.x;
    float s = 0.f, q = 0.f;
    for (int p = 0; p < BNP; p++) {
        s += g_part[p * 128 + c];
        q += g_part2[p * 128 + c];
    }
    float mu = s / (float)NN;
    float var = q / (float)NN - mu * mu;
    var = var > 0.f ? var : 0.f;
    g_mu[c] = mu;
    g_istd[c] = rsqrtf(var + 1e-5f);
    if (c == 0) g_asmax_bits = 0u;   // reset for next layer's asmax
}

// heads on g_buf1
__global__ void __launch_bounds__(256)
heads_kernel(const float* __restrict__ gam, const float* __restrict__ bet,
             const float* __restrict__ locW, const float* __restrict__ locb,
             const float* __restrict__ stdW, const float* __restrict__ stdb,
             float* __restrict__ out_loc, float* __restrict__ out_std) {
    __shared__ float sL[128 * 32];
    __shared__ float sS[128 * 32];
    for (int i = threadIdx.x; i < 4096; i += 256) { sL[i] = locW[i]; sS[i] = stdW[i]; }
    __syncthreads();
    int lane = threadIdx.x & 31;
    int warp = (blockIdx.x * blockDim.x + threadIdx.x) >> 5;
    int nw = (gridDim.x * blockDim.x) >> 5;
    float4 m4 = *(const float4*)&g_mu[lane * 4];
    float4 i4 = *(const float4*)&g_istd[lane * 4];
    float4 g4 = __ldg((const float4*)&gam[lane * 4]);
    float4 b4 = __ldg((const float4*)&bet[lane * 4]);
    float lb = __ldg(&locb[lane]);
    float sb = __ldg(&stdb[lane]);
    for (int r = warp; r < NN; r += nw) {
        float4 v = *(const float4*)&g_buf1[(size_t)r * 128 + lane * 4];
        float vr[4];
        vr[0] = bnlrelu(v.x, m4.x, i4.x, g4.x, b4.x);
        vr[1] = bnlrelu(v.y, m4.y, i4.y, g4.y, b4.y);
        vr[2] = bnlrelu(v.z, m4.z, i4.z, g4.z, b4.z);
        vr[3] = bnlrelu(v.w, m4.w, i4.w, g4.w, b4.w);
        float al = 0.f, as = 0.f;
#pragma unroll
        for (int k4 = 0; k4 < 32; k4++) {
#pragma unroll
            for (int q = 0; q < 4; q++) {
                float vk = __shfl_sync(0xffffffffu, vr[q], k4);
                int k = k4 * 4 + q;
                al = fmaf(vk, sL[k * 32 + lane], al);
                as = fmaf(vk, sS[k * 32 + lane], as);
            }
        }
        out_loc[(size_t)r * 32 + lane] = al + lb;
        float z = as + sb;
        float sp = (z > 0.f) ? z + log1pf(__expf(-z)) : log1pf(__expf(z));
        out_std[(size_t)r * 32 + lane] = sp + 1e-7f;
    }
}

// ---------------- launch ----------------
extern "C" void kernel_launch(void* const* d_in, const int* in_sizes, int n_in,
                              void* d_out, int out_size) {
    const float* x = (const float*)d_in[0];
    const int* edges = (const int*)d_in[1];
    const float* W0 = (const float*)d_in[2];
    const float* a_s0 = (const float*)d_in[3];
    const float* a_d0 = (const float*)d_in[4];
    const float* g0 = (const float*)d_in[5];
    const float* b0 = (const float*)d_in[6];
    const float* W1 = (const float*)d_in[7];
    const float* a_s1 = (const float*)d_in[8];
    const float* a_d1 = (const float*)d_in[9];
    const float* g1 = (const float*)d_in[10];
    const float* b1 = (const float*)d_in[11];
    const float* locW = (const float*)d_in[12];
    const float* locb = (const float*)d_in[13];
    const float* stdW = (const float*)d_in[14];
    const float* stdb = (const float*)d_in[15];

    float* out = (float*)d_out;
    float* out_loc = out;
    float* out_std = out + (size_t)NN * NOUT;
    float* out_l = out + 2 * (size_t)NN * NOUT;

    const int CH = (NN + 1023) / 1024;  // 98

    detect_kernel<<<1, 32>>>(edges);
    zero_int2_kernel<<<(NN + 255) / 256, 256>>>();
    w0prep_kernel<<<256, 256>>>(W0);
    rowsum_kernel<<<12500, 256>>>(x, out_l);
    gemm0_bf16x2_kernel<<<(NN + 127) / 128, 256>>>(x, a_s0, a_d0);

    // CSR build
    hist_kernel<<<(EE + 255) / 256, 256>>>(edges);
    scan1_kernel<<<CH, 1024>>>();
    scan2_kernel<<<1, 32>>>(CH);   // also resets asmax
    scan3_kernel<<<(NN + 255) / 256, 256>>>();
    scatter_kernel<<<(EE + 255) / 256, 256>>>(edges);

    // ---- layer 0 ----
    asmax_kernel<<<CH, 1024>>>();
    aggregate_kernel<<<12500, 256>>>();
    bn_stats_kernel<<<BNP, 128>>>();
    bn_finalize_kernel<<<1, 128>>>();  // also resets asmax

    // ---- layer 1 ----
    gemm1_kernel<<<(NN + 127) / 128, 256>>>(W1, g0, b0, a_s1, a_d1);
    asmax_kernel<<<CH, 1024>>>();
    aggregate_kernel<<<12500, 256>>>();
    bn_stats_kernel<<<BNP, 128>>>();
    bn_finalize_kernel<<<1, 128>>>();

    // ---- heads ----
    heads_kernel<<<2048, 256>>>(g1, b1, locW, locb, stdW, stdb, out_loc, out_std);
}